// round 7
// baseline (speedup 1.0000x reference)
#include <cuda_runtime.h>
#include <cuda_bf16.h>
#include <math.h>
#include <stdint.h>

#define Bb 2
#define Ts 2048
#define Dd 1024
#define Hh 16
#define DHd 64
#define MROWS (Bb*Ts)   // 4096

// ---------------------------------------------------------------------------
// Scratch (__device__ globals; allocation-free rule)
// ---------------------------------------------------------------------------
__device__ float g_qkv[(size_t)MROWS * 3 * Dd];          // [B*T, 3D]
__device__ float g_attn[(size_t)MROWS * Dd];             // [B*T, D]
__device__ __nv_bfloat16 g_qhi[(size_t)Bb*Hh*Ts*DHd];    // [b,h,t,d] (q*0.125)
__device__ __nv_bfloat16 g_qlo[(size_t)Bb*Hh*Ts*DHd];
__device__ __nv_bfloat16 g_khi[(size_t)Bb*Hh*Ts*DHd];    // [b,h,t,d]
__device__ __nv_bfloat16 g_klo[(size_t)Bb*Hh*Ts*DHd];
__device__ __nv_bfloat16 g_vthi[(size_t)Bb*Hh*DHd*Ts];   // [b,h,d,t] transposed
__device__ __nv_bfloat16 g_vtlo[(size_t)Bb*Hh*DHd*Ts];

// ---------------------------------------------------------------------------
// warp-mma helpers (baseline PTX, valid on plain sm_103 target)
// ---------------------------------------------------------------------------
__device__ __forceinline__ uint32_t smem_u32(const void* p) {
    uint32_t a;
    asm("{ .reg .u64 t; cvta.to.shared.u64 t, %1; cvt.u32.u64 %0, t; }"
        : "=r"(a) : "l"(p));
    return a;
}

__device__ __forceinline__ void mma_bf16(float* d, const uint32_t* a,
                                         uint32_t b0, uint32_t b1) {
    asm volatile(
        "mma.sync.aligned.m16n8k16.row.col.f32.bf16.bf16.f32 "
        "{%0,%1,%2,%3}, {%4,%5,%6,%7}, {%8,%9}, {%0,%1,%2,%3};"
        : "+f"(d[0]), "+f"(d[1]), "+f"(d[2]), "+f"(d[3])
        : "r"(a[0]), "r"(a[1]), "r"(a[2]), "r"(a[3]), "r"(b0), "r"(b1));
}

__device__ __forceinline__ void ldsm_x4(uint32_t addr, uint32_t* r) {
    asm volatile("ldmatrix.sync.aligned.m8n8.x4.shared.b16 {%0,%1,%2,%3}, [%4];"
        : "=r"(r[0]), "=r"(r[1]), "=r"(r[2]), "=r"(r[3]) : "r"(addr));
}

// pack two fp32 into bf16x2: lo -> lower half, hi -> upper half
__device__ __forceinline__ uint32_t packbf(float lo, float hi) {
    uint32_t r;
    asm("cvt.rn.bf16x2.f32 %0, %1, %2;" : "=r"(r) : "f"(hi), "f"(lo));
    return r;
}

// ---------------------------------------------------------------------------
// SGEMM (fp32, unchanged): C[M,N] = A[M,K] @ B[K,N]
// ---------------------------------------------------------------------------
__global__ __launch_bounds__(256) void sgemm128(const float* __restrict__ A,
                                                const float* __restrict__ Bw,
                                                float* __restrict__ C,
                                                int M, int N, int K) {
    constexpr int BM = 128, BN = 128, BK = 8;
    __shared__ float As[BK][BM];
    __shared__ float Bs[BK][BN];

    const int tid = threadIdx.x;
    const int bx = blockIdx.x, by = blockIdx.y;
    const int tx = tid & 15;
    const int ty = tid >> 4;

    const int arow = tid >> 1;
    const int acol = (tid & 1) * 4;
    const int brow = tid >> 5;
    const int bcol = (tid & 31) * 4;

    const float* Ap = A + (size_t)(by * BM + arow) * K + acol;
    const float* Bp = Bw + (size_t)brow * N + bx * BN + bcol;

    float acc[8][8];
    #pragma unroll
    for (int i = 0; i < 8; i++)
        #pragma unroll
        for (int j = 0; j < 8; j++) acc[i][j] = 0.0f;

    for (int k0 = 0; k0 < K; k0 += BK) {
        float4 a4 = *(const float4*)Ap;
        float4 b4 = *(const float4*)Bp;
        As[acol + 0][arow] = a4.x;
        As[acol + 1][arow] = a4.y;
        As[acol + 2][arow] = a4.z;
        As[acol + 3][arow] = a4.w;
        *(float4*)&Bs[brow][bcol] = b4;
        __syncthreads();

        #pragma unroll
        for (int kk = 0; kk < BK; kk++) {
            float am[8], bn[8];
            *(float4*)&am[0] = *(const float4*)&As[kk][ty * 8];
            *(float4*)&am[4] = *(const float4*)&As[kk][ty * 8 + 4];
            *(float4*)&bn[0] = *(const float4*)&Bs[kk][tx * 8];
            *(float4*)&bn[4] = *(const float4*)&Bs[kk][tx * 8 + 4];
            #pragma unroll
            for (int i = 0; i < 8; i++)
                #pragma unroll
                for (int j = 0; j < 8; j++)
                    acc[i][j] = fmaf(am[i], bn[j], acc[i][j]);
        }
        __syncthreads();
        Ap += BK;
        Bp += (size_t)BK * N;
    }

    float* Cp = C + (size_t)(by * BM + ty * 8) * N + bx * BN + tx * 8;
    #pragma unroll
    for (int i = 0; i < 8; i++) {
        *(float4*)(Cp + (size_t)i * N) =
            make_float4(acc[i][0], acc[i][1], acc[i][2], acc[i][3]);
        *(float4*)(Cp + (size_t)i * N + 4) =
            make_float4(acc[i][4], acc[i][5], acc[i][6], acc[i][7]);
    }
}

// ---------------------------------------------------------------------------
// RoPE + split into bf16 hi/lo operands (Q pre-scaled by 0.125; V transposed)
// ---------------------------------------------------------------------------
__global__ __launch_bounds__(256) void rope_split_kernel(
    const float* __restrict__ qkv,
    __nv_bfloat16* __restrict__ qhi, __nv_bfloat16* __restrict__ qlo,
    __nv_bfloat16* __restrict__ khi, __nv_bfloat16* __restrict__ klo,
    __nv_bfloat16* __restrict__ vthi, __nv_bfloat16* __restrict__ vtlo) {
    int idx = blockIdx.x * blockDim.x + threadIdx.x;
    int d = idx & 63;
    int t = (idx >> 6) & (Ts - 1);
    int h = (idx >> 17) & (Hh - 1);
    int b = idx >> 21;
    int bh = b * Hh + h;

    size_t base = ((size_t)(b * Ts + t)) * (3 * Dd) + h * DHd;
    float qv = qkv[base + d];
    float kv = qkv[base + Dd + d];
    float vv = qkv[base + 2 * Dd + d];

    int d2 = (d < 32) ? d + 32 : d - 32;
    float sgn = (d < 32) ? -1.0f : 1.0f;
    float qp = qkv[base + d2] * sgn;
    float kp = qkv[base + Dd + d2] * sgn;

    int fidx = d & 31;
    float inv = (float)exp2(-(double)fidx / 32.0 * 13.287712379549449);
    float ang = (float)t * inv;
    float c, s;
    sincosf(ang, &s, &c);

    float qr = (qv * c + qp * s) * 0.125f;   // fold softmax scale into q
    float kr = kv * c + kp * s;

    size_t oidx = (((size_t)bh) * Ts + t) * DHd + d;
    __nv_bfloat16 qh = __float2bfloat16_rn(qr);
    __nv_bfloat16 kh = __float2bfloat16_rn(kr);
    qhi[oidx] = qh; qlo[oidx] = __float2bfloat16_rn(qr - __bfloat162float(qh));
    khi[oidx] = kh; klo[oidx] = __float2bfloat16_rn(kr - __bfloat162float(kh));

    size_t vidx = (((size_t)bh) * DHd + d) * Ts + t;   // transposed
    __nv_bfloat16 vh = __float2bfloat16_rn(vv);
    vthi[vidx] = vh; vtlo[vidx] = __float2bfloat16_rn(vv - __bfloat162float(vh));
}

// ---------------------------------------------------------------------------
// Flash attention on warp-level bf16 HMMA (mma.sync m16n8k16), hi/lo split.
// CTA: 256 thr = 8 warps, 128 queries (16 rows/warp). K-tile = 64 keys.
// smem (32KB): Khi 0 | Klo 8K | VThi 16K | VTlo 24K  (Q staged there first)
// ---------------------------------------------------------------------------
__global__ __launch_bounds__(256) void attn_mma_kernel(
    const __nv_bfloat16* __restrict__ qhi, const __nv_bfloat16* __restrict__ qlo,
    const __nv_bfloat16* __restrict__ khi, const __nv_bfloat16* __restrict__ klo,
    const __nv_bfloat16* __restrict__ vthi, const __nv_bfloat16* __restrict__ vtlo,
    float* __restrict__ out) {
    __shared__ __align__(1024) char sm[32768];
    const int tid = threadIdx.x;
    const int w = tid >> 5, lane = tid & 31;
    const int qb = (int)gridDim.x - 1 - (int)blockIdx.x;   // heavy blocks first
    const int h = blockIdx.y, b = blockIdx.z;
    const int bh = b * Hh + h;
    const uint32_t sbase = smem_u32(sm);

    // ---- stage Q tile (hi @0, lo @16K), 128 rows x 128B, swizzled ----
    {
        const uint4* qh4 = (const uint4*)qhi + ((size_t)bh * Ts + qb * 128) * 8;
        const uint4* ql4 = (const uint4*)qlo + ((size_t)bh * Ts + qb * 128) * 8;
        #pragma unroll
        for (int i = 0; i < 4; i++) {
            int f = tid + i * 256;            // 0..1023
            int r = f >> 3, c = f & 7;
            uint32_t off = (r << 7) + (((uint32_t)(c ^ (r & 7))) << 4);
            *(uint4*)(sm + off)         = qh4[f];
            *(uint4*)(sm + 16384 + off) = ql4[f];
        }
    }
    __syncthreads();

    // ---- Q fragments (A-operand), 4 k-steps, hi+lo ----
    uint32_t qfh[4][4], qfl[4][4];
    #pragma unroll
    for (int ks = 0; ks < 4; ks++) {
        int r = w * 16 + (lane & 15);
        int chunk = ks * 2 + ((lane >> 4) & 1);
        uint32_t off = (r << 7) + (((uint32_t)(chunk ^ (r & 7))) << 4);
        ldsm_x4(sbase + off, qfh[ks]);
        ldsm_x4(sbase + 16384 + off, qfl[ks]);
    }
    __syncthreads();

    const int g = lane >> 2, tj = lane & 3;
    const int qg0 = qb * 128 + w * 16 + g;
    const int qg1 = qg0 + 8;

    float oa[8][4];
    #pragma unroll
    for (int nf = 0; nf < 8; nf++)
        #pragma unroll
        for (int e = 0; e < 4; e++) oa[nf][e] = 0.0f;
    float m_0 = -INFINITY, m_1 = -INFINITY, l_0 = 0.0f, l_1 = 0.0f;

    const uint4* kh4 = (const uint4*)khi + ((size_t)bh * Ts) * 8;
    const uint4* kl4 = (const uint4*)klo + ((size_t)bh * Ts) * 8;
    const uint4* vh4 = (const uint4*)vthi + ((size_t)bh * DHd) * 256;
    const uint4* vl4 = (const uint4*)vtlo + ((size_t)bh * DHd) * 256;

    const int nkt = 2 * qb + 2;
    for (int kt = 0; kt < nkt; kt++) {
        __syncthreads();
        // ---- stage K(hi/lo) and V^T(hi/lo) tiles, swizzled ----
        #pragma unroll
        for (int i = 0; i < 2; i++) {
            int f = tid + i * 256;            // 0..511
            int r = f >> 3, c = f & 7;
            uint32_t off = (r << 7) + (((uint32_t)(c ^ (r & 7))) << 4);
            size_t kidx = (size_t)(kt * 64 + r) * 8 + c;
            *(uint4*)(sm + off)         = kh4[kidx];
            *(uint4*)(sm + 8192 + off)  = kl4[kidx];
            size_t vidx = (size_t)r * 256 + kt * 8 + c;
            *(uint4*)(sm + 16384 + off) = vh4[vidx];
            *(uint4*)(sm + 24576 + off) = vl4[vidx];
        }
        __syncthreads();

        // ---- S = Q K^T (3-term hi/lo split) ----
        float sa[8][4];
        #pragma unroll
        for (int nf = 0; nf < 8; nf++)
            #pragma unroll
            for (int e = 0; e < 4; e++) sa[nf][e] = 0.0f;

        #pragma unroll
        for (int k2 = 0; k2 < 2; k2++) {
            #pragma unroll
            for (int nf = 0; nf < 8; nf++) {
                int rr = nf * 8 + (lane & 7);
                int chunk = k2 * 4 + ((lane >> 3) & 3);
                uint32_t off = (rr << 7) + (((uint32_t)(chunk ^ (rr & 7))) << 4);
                uint32_t bhv[4], blv[4];
                ldsm_x4(sbase + off, bhv);
                ldsm_x4(sbase + 8192 + off, blv);
                mma_bf16(sa[nf], qfh[2 * k2],     bhv[0], bhv[1]);
                mma_bf16(sa[nf], qfh[2 * k2],     blv[0], blv[1]);
                mma_bf16(sa[nf], qfl[2 * k2],     bhv[0], bhv[1]);
                mma_bf16(sa[nf], qfh[2 * k2 + 1], bhv[2], bhv[3]);
                mma_bf16(sa[nf], qfh[2 * k2 + 1], blv[2], blv[3]);
                mma_bf16(sa[nf], qfl[2 * k2 + 1], bhv[2], bhv[3]);
            }
        }

        // ---- causal mask + online softmax (registers only) ----
        float tmax0 = -INFINITY, tmax1 = -INFINITY;
        #pragma unroll
        for (int nf = 0; nf < 8; nf++) {
            int kg = kt * 64 + nf * 8 + 2 * tj;
            if (kg     > qg0) sa[nf][0] = -INFINITY;
            if (kg + 1 > qg0) sa[nf][1] = -INFINITY;
            if (kg     > qg1) sa[nf][2] = -INFINITY;
            if (kg + 1 > qg1) sa[nf][3] = -INFINITY;
            tmax0 = fmaxf(tmax0, fmaxf(sa[nf][0], sa[nf][1]));
            tmax1 = fmaxf(tmax1, fmaxf(sa[nf][2], sa[nf][3]));
        }
        tmax0 = fmaxf(tmax0, __shfl_xor_sync(0xffffffffu, tmax0, 1));
        tmax0 = fmaxf(tmax0, __shfl_xor_sync(0xffffffffu, tmax0, 2));
        tmax1 = fmaxf(tmax1, __shfl_xor_sync(0xffffffffu, tmax1, 1));
        tmax1 = fmaxf(tmax1, __shfl_xor_sync(0xffffffffu, tmax1, 2));

        float mn0 = fmaxf(m_0, tmax0), mn1 = fmaxf(m_1, tmax1);
        float c0 = __expf(m_0 - mn0), c1 = __expf(m_1 - mn1);
        m_0 = mn0; m_1 = mn1;
        l_0 *= c0; l_1 *= c1;
        #pragma unroll
        for (int nf = 0; nf < 8; nf++) {
            oa[nf][0] *= c0; oa[nf][1] *= c0;
            oa[nf][2] *= c1; oa[nf][3] *= c1;
        }

        // P = exp(S - m), packed into A-fragments (hi + residual lo)
        uint32_t ph[4][4], pl[4][4];
        #pragma unroll
        for (int nf = 0; nf < 8; nf++) {
            float p0 = __expf(sa[nf][0] - m_0);
            float p1 = __expf(sa[nf][1] - m_0);
            float p2 = __expf(sa[nf][2] - m_1);
            float p3 = __expf(sa[nf][3] - m_1);
            l_0 += p0 + p1; l_1 += p2 + p3;
            uint32_t u01 = packbf(p0, p1);
            uint32_t u23 = packbf(p2, p3);
            float h0 = __uint_as_float(u01 << 16);
            float h1 = __uint_as_float(u01 & 0xffff0000u);
            float h2 = __uint_as_float(u23 << 16);
            float h3 = __uint_as_float(u23 & 0xffff0000u);
            int ks = nf >> 1, hf = nf & 1;
            ph[ks][hf * 2 + 0] = u01;
            ph[ks][hf * 2 + 1] = u23;
            pl[ks][hf * 2 + 0] = packbf(p0 - h0, p1 - h1);
            pl[ks][hf * 2 + 1] = packbf(p2 - h2, p3 - h3);
        }

        // ---- O += P V (3-term hi/lo split) ----
        #pragma unroll
        for (int k2 = 0; k2 < 2; k2++) {
            #pragma unroll
            for (int nf = 0; nf < 8; nf++) {
                int rr = nf * 8 + (lane & 7);
                int chunk = k2 * 4 + ((lane >> 3) & 3);
                uint32_t off = (rr << 7) + (((uint32_t)(chunk ^ (rr & 7))) << 4);
                uint32_t bhv[4], blv[4];
                ldsm_x4(sbase + 16384 + off, bhv);
                ldsm_x4(sbase + 24576 + off, blv);
                mma_bf16(oa[nf], ph[2 * k2],     bhv[0], bhv[1]);
                mma_bf16(oa[nf], ph[2 * k2],     blv[0], blv[1]);
                mma_bf16(oa[nf], pl[2 * k2],     bhv[0], bhv[1]);
                mma_bf16(oa[nf], ph[2 * k2 + 1], bhv[2], bhv[3]);
                mma_bf16(oa[nf], ph[2 * k2 + 1], blv[2], blv[3]);
                mma_bf16(oa[nf], pl[2 * k2 + 1], bhv[2], bhv[3]);
            }
        }
    }

    // ---- epilogue ----
    l_0 += __shfl_xor_sync(0xffffffffu, l_0, 1);
    l_0 += __shfl_xor_sync(0xffffffffu, l_0, 2);
    l_1 += __shfl_xor_sync(0xffffffffu, l_1, 1);
    l_1 += __shfl_xor_sync(0xffffffffu, l_1, 2);
    float i0 = 1.0f / l_0, i1 = 1.0f / l_1;

    float* o0 = out + ((size_t)(b * Ts) + qb * 128 + w * 16 + g) * Dd + h * DHd;
    float* o1 = o0 + (size_t)8 * Dd;
    #pragma unroll
    for (int nf = 0; nf < 8; nf++) {
        int col = nf * 8 + 2 * tj;
        *(float2*)(o0 + col) = make_float2(oa[nf][0] * i0, oa[nf][1] * i0);
        *(float2*)(o1 + col) = make_float2(oa[nf][2] * i1, oa[nf][3] * i1);
    }
}

// ---------------------------------------------------------------------------
extern "C" void kernel_launch(void* const* d_in, const int* in_sizes, int n_in,
                              void* d_out, int out_size) {
    const float* x     = (const float*)d_in[0];
    const float* w_qkv = (const float*)d_in[1];
    const float* w_out = (const float*)d_in[2];
    float* out = (float*)d_out;

    float *qkv, *attn;
    __nv_bfloat16 *qhi, *qlo, *khi, *klo, *vthi, *vtlo;
    cudaGetSymbolAddress((void**)&qkv,  g_qkv);
    cudaGetSymbolAddress((void**)&attn, g_attn);
    cudaGetSymbolAddress((void**)&qhi,  g_qhi);
    cudaGetSymbolAddress((void**)&qlo,  g_qlo);
    cudaGetSymbolAddress((void**)&khi,  g_khi);
    cudaGetSymbolAddress((void**)&klo,  g_klo);
    cudaGetSymbolAddress((void**)&vthi, g_vthi);
    cudaGetSymbolAddress((void**)&vtlo, g_vtlo);

    sgemm128<<<dim3((3 * Dd) / 128, MROWS / 128), 256>>>(x, w_qkv, qkv,
                                                         MROWS, 3 * Dd, Dd);
    rope_split_kernel<<<(Bb * Hh * Ts * DHd) / 256, 256>>>(
        qkv, qhi, qlo, khi, klo, vthi, vtlo);
    attn_mma_kernel<<<dim3(Ts / 128, Hh, Bb), 256>>>(
        qhi, qlo, khi, klo, vthi, vtlo, attn);
    sgemm128<<<dim3(Dd / 128, MROWS / 128), 256>>>(attn, w_out, out,
                                                   MROWS, Dd, Dd);
}

// round 8
// speedup vs baseline: 1.0021x; 1.0021x over previous
#include <cuda_runtime.h>
#include <cuda_bf16.h>
#include <math.h>
#include <stdint.h>

#define Bb 2
#define Ts 2048
#define Dd 1024
#define Hh 16
#define DHd 64
#define MROWS (Bb*Ts)   // 4096

// ---------------------------------------------------------------------------
// Scratch (__device__ globals; allocation-free rule)
// ---------------------------------------------------------------------------
__device__ float g_qkv[(size_t)MROWS * 3 * Dd];          // [B*T, 3D]
__device__ float g_attn[(size_t)MROWS * Dd];             // [B*T, D]
__device__ __nv_bfloat16 g_qhi[(size_t)Bb*Hh*Ts*DHd];    // [b,h,t,d] (q*0.125)
__device__ __nv_bfloat16 g_qlo[(size_t)Bb*Hh*Ts*DHd];
__device__ __nv_bfloat16 g_khi[(size_t)Bb*Hh*Ts*DHd];    // [b,h,t,d]
__device__ __nv_bfloat16 g_klo[(size_t)Bb*Hh*Ts*DHd];
__device__ __nv_bfloat16 g_vthi[(size_t)Bb*Hh*DHd*Ts];   // [b,h,d,t] transposed
__device__ __nv_bfloat16 g_vtlo[(size_t)Bb*Hh*DHd*Ts];

// ---------------------------------------------------------------------------
// warp-mma helpers (baseline PTX, valid on plain sm_103 target)
// ---------------------------------------------------------------------------
__device__ __forceinline__ uint32_t smem_u32(const void* p) {
    uint32_t a;
    asm("{ .reg .u64 t; cvta.to.shared.u64 t, %1; cvt.u32.u64 %0, t; }"
        : "=r"(a) : "l"(p));
    return a;
}

__device__ __forceinline__ void mma_bf16(float* d, const uint32_t* a,
                                         uint32_t b0, uint32_t b1) {
    asm volatile(
        "mma.sync.aligned.m16n8k16.row.col.f32.bf16.bf16.f32 "
        "{%0,%1,%2,%3}, {%4,%5,%6,%7}, {%8,%9}, {%0,%1,%2,%3};"
        : "+f"(d[0]), "+f"(d[1]), "+f"(d[2]), "+f"(d[3])
        : "r"(a[0]), "r"(a[1]), "r"(a[2]), "r"(a[3]), "r"(b0), "r"(b1));
}

__device__ __forceinline__ void ldsm_x4(uint32_t addr, uint32_t* r) {
    asm volatile("ldmatrix.sync.aligned.m8n8.x4.shared.b16 {%0,%1,%2,%3}, [%4];"
        : "=r"(r[0]), "=r"(r[1]), "=r"(r[2]), "=r"(r[3]) : "r"(addr));
}

// pack two fp32 into bf16x2: lo -> lower half, hi -> upper half
__device__ __forceinline__ uint32_t packbf(float lo, float hi) {
    uint32_t r;
    asm("cvt.rn.bf16x2.f32 %0, %1, %2;" : "=r"(r) : "f"(hi), "f"(lo));
    return r;
}

// ---------------------------------------------------------------------------
// SGEMM (fp32, unchanged): C[M,N] = A[M,K] @ B[K,N]
// ---------------------------------------------------------------------------
__global__ __launch_bounds__(256) void sgemm128(const float* __restrict__ A,
                                                const float* __restrict__ Bw,
                                                float* __restrict__ C,
                                                int M, int N, int K) {
    constexpr int BM = 128, BN = 128, BK = 8;
    __shared__ float As[BK][BM];
    __shared__ float Bs[BK][BN];

    const int tid = threadIdx.x;
    const int bx = blockIdx.x, by = blockIdx.y;
    const int tx = tid & 15;
    const int ty = tid >> 4;

    const int arow = tid >> 1;
    const int acol = (tid & 1) * 4;
    const int brow = tid >> 5;
    const int bcol = (tid & 31) * 4;

    const float* Ap = A + (size_t)(by * BM + arow) * K + acol;
    const float* Bp = Bw + (size_t)brow * N + bx * BN + bcol;

    float acc[8][8];
    #pragma unroll
    for (int i = 0; i < 8; i++)
        #pragma unroll
        for (int j = 0; j < 8; j++) acc[i][j] = 0.0f;

    for (int k0 = 0; k0 < K; k0 += BK) {
        float4 a4 = *(const float4*)Ap;
        float4 b4 = *(const float4*)Bp;
        As[acol + 0][arow] = a4.x;
        As[acol + 1][arow] = a4.y;
        As[acol + 2][arow] = a4.z;
        As[acol + 3][arow] = a4.w;
        *(float4*)&Bs[brow][bcol] = b4;
        __syncthreads();

        #pragma unroll
        for (int kk = 0; kk < BK; kk++) {
            float am[8], bn[8];
            *(float4*)&am[0] = *(const float4*)&As[kk][ty * 8];
            *(float4*)&am[4] = *(const float4*)&As[kk][ty * 8 + 4];
            *(float4*)&bn[0] = *(const float4*)&Bs[kk][tx * 8];
            *(float4*)&bn[4] = *(const float4*)&Bs[kk][tx * 8 + 4];
            #pragma unroll
            for (int i = 0; i < 8; i++)
                #pragma unroll
                for (int j = 0; j < 8; j++)
                    acc[i][j] = fmaf(am[i], bn[j], acc[i][j]);
        }
        __syncthreads();
        Ap += BK;
        Bp += (size_t)BK * N;
    }

    float* Cp = C + (size_t)(by * BM + ty * 8) * N + bx * BN + tx * 8;
    #pragma unroll
    for (int i = 0; i < 8; i++) {
        *(float4*)(Cp + (size_t)i * N) =
            make_float4(acc[i][0], acc[i][1], acc[i][2], acc[i][3]);
        *(float4*)(Cp + (size_t)i * N + 4) =
            make_float4(acc[i][4], acc[i][5], acc[i][6], acc[i][7]);
    }
}

// ---------------------------------------------------------------------------
// RoPE + split into bf16 hi/lo operands (Q pre-scaled by 0.125; V transposed)
// ---------------------------------------------------------------------------
__global__ __launch_bounds__(256) void rope_split_kernel(
    const float* __restrict__ qkv,
    __nv_bfloat16* __restrict__ qhi, __nv_bfloat16* __restrict__ qlo,
    __nv_bfloat16* __restrict__ khi, __nv_bfloat16* __restrict__ klo,
    __nv_bfloat16* __restrict__ vthi, __nv_bfloat16* __restrict__ vtlo) {
    int idx = blockIdx.x * blockDim.x + threadIdx.x;
    int d = idx & 63;
    int t = (idx >> 6) & (Ts - 1);
    int h = (idx >> 17) & (Hh - 1);
    int b = idx >> 21;
    int bh = b * Hh + h;

    size_t base = ((size_t)(b * Ts + t)) * (3 * Dd) + h * DHd;
    float qv = qkv[base + d];
    float kv = qkv[base + Dd + d];
    float vv = qkv[base + 2 * Dd + d];

    int d2 = (d < 32) ? d + 32 : d - 32;
    float sgn = (d < 32) ? -1.0f : 1.0f;
    float qp = qkv[base + d2] * sgn;
    float kp = qkv[base + Dd + d2] * sgn;

    int fidx = d & 31;
    float inv = (float)exp2(-(double)fidx / 32.0 * 13.287712379549449);
    float ang = (float)t * inv;
    float c, s;
    sincosf(ang, &s, &c);

    float qr = (qv * c + qp * s) * 0.125f;   // fold softmax scale into q
    float kr = kv * c + kp * s;

    size_t oidx = (((size_t)bh) * Ts + t) * DHd + d;
    __nv_bfloat16 qh = __float2bfloat16_rn(qr);
    __nv_bfloat16 kh = __float2bfloat16_rn(kr);
    qhi[oidx] = qh; qlo[oidx] = __float2bfloat16_rn(qr - __bfloat162float(qh));
    khi[oidx] = kh; klo[oidx] = __float2bfloat16_rn(kr - __bfloat162float(kh));

    size_t vidx = (((size_t)bh) * DHd + d) * Ts + t;   // transposed
    __nv_bfloat16 vh = __float2bfloat16_rn(vv);
    vthi[vidx] = vh; vtlo[vidx] = __float2bfloat16_rn(vv - __bfloat162float(vh));
}

// ---------------------------------------------------------------------------
// Flash attention on warp-level bf16 HMMA (mma.sync m16n8k16), hi/lo split.
// CTA: 256 thr = 8 warps, 128 queries (16 rows/warp). K-tile = 64 keys.
// smem (32KB): Khi 0 | Klo 8K | VThi 16K | VTlo 24K  (Q staged there first)
// ---------------------------------------------------------------------------
__global__ __launch_bounds__(256) void attn_mma_kernel(
    const __nv_bfloat16* __restrict__ qhi, const __nv_bfloat16* __restrict__ qlo,
    const __nv_bfloat16* __restrict__ khi, const __nv_bfloat16* __restrict__ klo,
    const __nv_bfloat16* __restrict__ vthi, const __nv_bfloat16* __restrict__ vtlo,
    float* __restrict__ out) {
    __shared__ __align__(1024) char sm[32768];
    const int tid = threadIdx.x;
    const int w = tid >> 5, lane = tid & 31;
    const int qb = (int)gridDim.x - 1 - (int)blockIdx.x;   // heavy blocks first
    const int h = blockIdx.y, b = blockIdx.z;
    const int bh = b * Hh + h;
    const uint32_t sbase = smem_u32(sm);

    // ---- stage Q tile (hi @0, lo @16K), 128 rows x 128B, swizzled ----
    {
        const uint4* qh4 = (const uint4*)qhi + ((size_t)bh * Ts + qb * 128) * 8;
        const uint4* ql4 = (const uint4*)qlo + ((size_t)bh * Ts + qb * 128) * 8;
        #pragma unroll
        for (int i = 0; i < 4; i++) {
            int f = tid + i * 256;            // 0..1023
            int r = f >> 3, c = f & 7;
            uint32_t off = (r << 7) + (((uint32_t)(c ^ (r & 7))) << 4);
            *(uint4*)(sm + off)         = qh4[f];
            *(uint4*)(sm + 16384 + off) = ql4[f];
        }
    }
    __syncthreads();

    // ---- Q fragments (A-operand), 4 k-steps, hi+lo ----
    uint32_t qfh[4][4], qfl[4][4];
    #pragma unroll
    for (int ks = 0; ks < 4; ks++) {
        int r = w * 16 + (lane & 15);
        int chunk = ks * 2 + ((lane >> 4) & 1);
        uint32_t off = (r << 7) + (((uint32_t)(chunk ^ (r & 7))) << 4);
        ldsm_x4(sbase + off, qfh[ks]);
        ldsm_x4(sbase + 16384 + off, qfl[ks]);
    }
    __syncthreads();

    const int g = lane >> 2, tj = lane & 3;
    const int qg0 = qb * 128 + w * 16 + g;
    const int qg1 = qg0 + 8;

    float oa[8][4];
    #pragma unroll
    for (int nf = 0; nf < 8; nf++)
        #pragma unroll
        for (int e = 0; e < 4; e++) oa[nf][e] = 0.0f;
    float m_0 = -INFINITY, m_1 = -INFINITY, l_0 = 0.0f, l_1 = 0.0f;

    const uint4* kh4 = (const uint4*)khi + ((size_t)bh * Ts) * 8;
    const uint4* kl4 = (const uint4*)klo + ((size_t)bh * Ts) * 8;
    const uint4* vh4 = (const uint4*)vthi + ((size_t)bh * DHd) * 256;
    const uint4* vl4 = (const uint4*)vtlo + ((size_t)bh * DHd) * 256;

    const int nkt = 2 * qb + 2;
    for (int kt = 0; kt < nkt; kt++) {
        __syncthreads();
        // ---- stage K(hi/lo) and V^T(hi/lo) tiles, swizzled ----
        #pragma unroll
        for (int i = 0; i < 2; i++) {
            int f = tid + i * 256;            // 0..511
            int r = f >> 3, c = f & 7;
            uint32_t off = (r << 7) + (((uint32_t)(c ^ (r & 7))) << 4);
            size_t kidx = (size_t)(kt * 64 + r) * 8 + c;
            *(uint4*)(sm + off)         = kh4[kidx];
            *(uint4*)(sm + 8192 + off)  = kl4[kidx];
            size_t vidx = (size_t)r * 256 + kt * 8 + c;
            *(uint4*)(sm + 16384 + off) = vh4[vidx];
            *(uint4*)(sm + 24576 + off) = vl4[vidx];
        }
        __syncthreads();

        // ---- S = Q K^T (3-term hi/lo split) ----
        float sa[8][4];
        #pragma unroll
        for (int nf = 0; nf < 8; nf++)
            #pragma unroll
            for (int e = 0; e < 4; e++) sa[nf][e] = 0.0f;

        #pragma unroll
        for (int k2 = 0; k2 < 2; k2++) {
            #pragma unroll
            for (int nf = 0; nf < 8; nf++) {
                int rr = nf * 8 + (lane & 7);
                int chunk = k2 * 4 + ((lane >> 3) & 3);
                uint32_t off = (rr << 7) + (((uint32_t)(chunk ^ (rr & 7))) << 4);
                uint32_t bhv[4], blv[4];
                ldsm_x4(sbase + off, bhv);
                ldsm_x4(sbase + 8192 + off, blv);
                mma_bf16(sa[nf], qfh[2 * k2],     bhv[0], bhv[1]);
                mma_bf16(sa[nf], qfh[2 * k2],     blv[0], blv[1]);
                mma_bf16(sa[nf], qfl[2 * k2],     bhv[0], bhv[1]);
                mma_bf16(sa[nf], qfh[2 * k2 + 1], bhv[2], bhv[3]);
                mma_bf16(sa[nf], qfh[2 * k2 + 1], blv[2], blv[3]);
                mma_bf16(sa[nf], qfl[2 * k2 + 1], bhv[2], bhv[3]);
            }
        }

        // ---- causal mask + online softmax (registers only) ----
        float tmax0 = -INFINITY, tmax1 = -INFINITY;
        #pragma unroll
        for (int nf = 0; nf < 8; nf++) {
            int kg = kt * 64 + nf * 8 + 2 * tj;
            if (kg     > qg0) sa[nf][0] = -INFINITY;
            if (kg + 1 > qg0) sa[nf][1] = -INFINITY;
            if (kg     > qg1) sa[nf][2] = -INFINITY;
            if (kg + 1 > qg1) sa[nf][3] = -INFINITY;
            tmax0 = fmaxf(tmax0, fmaxf(sa[nf][0], sa[nf][1]));
            tmax1 = fmaxf(tmax1, fmaxf(sa[nf][2], sa[nf][3]));
        }
        tmax0 = fmaxf(tmax0, __shfl_xor_sync(0xffffffffu, tmax0, 1));
        tmax0 = fmaxf(tmax0, __shfl_xor_sync(0xffffffffu, tmax0, 2));
        tmax1 = fmaxf(tmax1, __shfl_xor_sync(0xffffffffu, tmax1, 1));
        tmax1 = fmaxf(tmax1, __shfl_xor_sync(0xffffffffu, tmax1, 2));

        float mn0 = fmaxf(m_0, tmax0), mn1 = fmaxf(m_1, tmax1);
        float c0 = __expf(m_0 - mn0), c1 = __expf(m_1 - mn1);
        m_0 = mn0; m_1 = mn1;
        l_0 *= c0; l_1 *= c1;
        #pragma unroll
        for (int nf = 0; nf < 8; nf++) {
            oa[nf][0] *= c0; oa[nf][1] *= c0;
            oa[nf][2] *= c1; oa[nf][3] *= c1;
        }

        // P = exp(S - m), packed into A-fragments (hi + residual lo)
        uint32_t ph[4][4], pl[4][4];
        #pragma unroll
        for (int nf = 0; nf < 8; nf++) {
            float p0 = __expf(sa[nf][0] - m_0);
            float p1 = __expf(sa[nf][1] - m_0);
            float p2 = __expf(sa[nf][2] - m_1);
            float p3 = __expf(sa[nf][3] - m_1);
            l_0 += p0 + p1; l_1 += p2 + p3;
            uint32_t u01 = packbf(p0, p1);
            uint32_t u23 = packbf(p2, p3);
            float h0 = __uint_as_float(u01 << 16);
            float h1 = __uint_as_float(u01 & 0xffff0000u);
            float h2 = __uint_as_float(u23 << 16);
            float h3 = __uint_as_float(u23 & 0xffff0000u);
            int ks = nf >> 1, hf = nf & 1;
            ph[ks][hf * 2 + 0] = u01;
            ph[ks][hf * 2 + 1] = u23;
            pl[ks][hf * 2 + 0] = packbf(p0 - h0, p1 - h1);
            pl[ks][hf * 2 + 1] = packbf(p2 - h2, p3 - h3);
        }

        // ---- O += P V (3-term hi/lo split) ----
        #pragma unroll
        for (int k2 = 0; k2 < 2; k2++) {
            #pragma unroll
            for (int nf = 0; nf < 8; nf++) {
                int rr = nf * 8 + (lane & 7);
                int chunk = k2 * 4 + ((lane >> 3) & 3);
                uint32_t off = (rr << 7) + (((uint32_t)(chunk ^ (rr & 7))) << 4);
                uint32_t bhv[4], blv[4];
                ldsm_x4(sbase + 16384 + off, bhv);
                ldsm_x4(sbase + 24576 + off, blv);
                mma_bf16(oa[nf], ph[2 * k2],     bhv[0], bhv[1]);
                mma_bf16(oa[nf], ph[2 * k2],     blv[0], blv[1]);
                mma_bf16(oa[nf], pl[2 * k2],     bhv[0], bhv[1]);
                mma_bf16(oa[nf], ph[2 * k2 + 1], bhv[2], bhv[3]);
                mma_bf16(oa[nf], ph[2 * k2 + 1], blv[2], blv[3]);
                mma_bf16(oa[nf], pl[2 * k2 + 1], bhv[2], bhv[3]);
            }
        }
    }

    // ---- epilogue ----
    l_0 += __shfl_xor_sync(0xffffffffu, l_0, 1);
    l_0 += __shfl_xor_sync(0xffffffffu, l_0, 2);
    l_1 += __shfl_xor_sync(0xffffffffu, l_1, 1);
    l_1 += __shfl_xor_sync(0xffffffffu, l_1, 2);
    float i0 = 1.0f / l_0, i1 = 1.0f / l_1;

    float* o0 = out + ((size_t)(b * Ts) + qb * 128 + w * 16 + g) * Dd + h * DHd;
    float* o1 = o0 + (size_t)8 * Dd;
    #pragma unroll
    for (int nf = 0; nf < 8; nf++) {
        int col = nf * 8 + 2 * tj;
        *(float2*)(o0 + col) = make_float2(oa[nf][0] * i0, oa[nf][1] * i0);
        *(float2*)(o1 + col) = make_float2(oa[nf][2] * i1, oa[nf][3] * i1);
    }
}

// ---------------------------------------------------------------------------
extern "C" void kernel_launch(void* const* d_in, const int* in_sizes, int n_in,
                              void* d_out, int out_size) {
    const float* x     = (const float*)d_in[0];
    const float* w_qkv = (const float*)d_in[1];
    const float* w_out = (const float*)d_in[2];
    float* out = (float*)d_out;

    float *qkv, *attn;
    __nv_bfloat16 *qhi, *qlo, *khi, *klo, *vthi, *vtlo;
    cudaGetSymbolAddress((void**)&qkv,  g_qkv);
    cudaGetSymbolAddress((void**)&attn, g_attn);
    cudaGetSymbolAddress((void**)&qhi,  g_qhi);
    cudaGetSymbolAddress((void**)&qlo,  g_qlo);
    cudaGetSymbolAddress((void**)&khi,  g_khi);
    cudaGetSymbolAddress((void**)&klo,  g_klo);
    cudaGetSymbolAddress((void**)&vthi, g_vthi);
    cudaGetSymbolAddress((void**)&vtlo, g_vtlo);

    sgemm128<<<dim3((3 * Dd) / 128, MROWS / 128), 256>>>(x, w_qkv, qkv,
                                                         MROWS, 3 * Dd, Dd);
    rope_split_kernel<<<(Bb * Hh * Ts * DHd) / 256, 256>>>(
        qkv, qhi, qlo, khi, klo, vthi, vtlo);
    attn_mma_kernel<<<dim3(Ts / 128, Hh, Bb), 256>>>(
        qhi, qlo, khi, klo, vthi, vtlo, attn);
    sgemm128<<<dim3(Dd / 128, MROWS / 128), 256>>>(attn, w_out, out,
                                                   MROWS, Dd, Dd);
}